// round 8
// baseline (speedup 1.0000x reference)
#include <cuda_runtime.h>
#include <cstdint>
#include <cstddef>

// ============================================================================
// RecurrentLegendreLayer via 3xBF16-split mma.sync (HMMA) GEMM.
//   out[b,o] = sum_{f,i} P_f(x[b,i]) * W[f,i,o] + bias[o]
// f=0 folded into bias => GEMM M=16384, N=512, K=4096.
// chunk c = ib*8 + (f-1), f in 1..8.  Stage = 2 chunks, one barrier.
// R7: recurrence state reconstructed from smem A tiles (frees 16 regs),
//     pass order (Ah*Bh, Ah*Bl, Al*Bh) to front-load B ldmatrix loads.
// ============================================================================

#define NSTG    64
#define BM      128
#define BN      256
#define NTHR    512

#define APITCH  80
#define ATILE   10240
#define BPITCH  528
#define BTILE   16896
#define SM_A    0
#define SM_B    81920
#define SMEM_TOTAL 217088

__device__ uint32_t g_B[2097152];    // 8.4 MB prepared W halves
__device__ float    g_bias2[512];    // bias + sum_i W[0,i,:]

// ---------------------------------------------------------------- helpers ---
__device__ __forceinline__ uint32_t smem_u32(const void* p) {
    return (uint32_t)__cvta_generic_to_shared(p);
}
__device__ __forceinline__ void cp_async16(uint32_t dst, const void* src) {
    asm volatile("cp.async.cg.shared.global [%0], [%1], 16;"
                 :: "r"(dst), "l"(__cvta_generic_to_global(src)));
}
__device__ __forceinline__ void cp_commit() { asm volatile("cp.async.commit_group;"); }
__device__ __forceinline__ void cp_wait0() {
    asm volatile("cp.async.wait_group 0;" ::: "memory");
}
__device__ __forceinline__ void ldsm_x4(uint32_t* r, uint32_t addr) {
    asm volatile("ldmatrix.sync.aligned.m8n8.x4.shared.b16 {%0,%1,%2,%3}, [%4];"
                 : "=r"(r[0]), "=r"(r[1]), "=r"(r[2]), "=r"(r[3]) : "r"(addr));
}
__device__ __forceinline__ void ldsm_x4_t(uint32_t* r, uint32_t addr) {
    asm volatile("ldmatrix.sync.aligned.m8n8.x4.trans.shared.b16 {%0,%1,%2,%3}, [%4];"
                 : "=r"(r[0]), "=r"(r[1]), "=r"(r[2]), "=r"(r[3]) : "r"(addr));
}
__device__ __forceinline__ void mma16816(float* c, const uint32_t* a,
                                         uint32_t b0, uint32_t b1) {
    asm volatile(
        "mma.sync.aligned.m16n8k16.row.col.f32.bf16.bf16.f32 "
        "{%0,%1,%2,%3}, {%4,%5,%6,%7}, {%8,%9}, {%0,%1,%2,%3};"
        : "+f"(c[0]), "+f"(c[1]), "+f"(c[2]), "+f"(c[3])
        : "r"(a[0]), "r"(a[1]), "r"(a[2]), "r"(a[3]), "r"(b0), "r"(b1));
}
__device__ __forceinline__ uint32_t pack_lo_bf16(float a0, float a1) {
    uint32_t d;
    asm("cvt.rn.bf16x2.f32 %0, %1, %2;" : "=r"(d) : "f"(a1), "f"(a0));
    return d;
}
// reconstruct 2 fp32 values from packed hi/lo bf16x2 words
__device__ __forceinline__ void unsplit2(uint32_t hw, uint32_t lw,
                                         float& a0, float& a1) {
    a0 = __uint_as_float(hw << 16)        + __uint_as_float(lw << 16);
    a1 = __uint_as_float(hw & 0xffff0000u) + __uint_as_float(lw & 0xffff0000u);
}

// ---------------------------------------------------------------- prepass ---
__global__ void leg_prep_kernel(const float* __restrict__ w) {
    uint32_t t = blockIdx.x * 256 + threadIdx.x;       // word id, 2097152 total
    uint32_t n2 = t & 255;
    uint32_t q  = t >> 8;
    uint32_t k  = q & 31;
    uint32_t hl = (q >> 5) & 1;
    uint32_t c  = q >> 6;                              // 0..127
    uint32_t f  = (c & 7) + 1;                         // 1..8
    uint32_t ib = c >> 3;
    size_t widx = ((size_t)(f * 512 + ib * 32 + k)) * 512 + n2 * 2;
    float w0 = w[widx], w1 = w[widx + 1];
    uint32_t b0 = __float_as_uint(w0) + 0x8000u;
    uint32_t b1 = __float_as_uint(w1) + 0x8000u;
    uint32_t word;
    if (hl == 0) {
        word = (b0 >> 16) | (b1 & 0xffff0000u);
    } else {
        float h0 = __uint_as_float(b0 & 0xffff0000u);
        float h1 = __uint_as_float(b1 & 0xffff0000u);
        word = pack_lo_bf16(w0 - h0, w1 - h1);
    }
    g_B[t] = word;
}

__global__ void leg_bias_kernel(const float* __restrict__ w,
                                const float* __restrict__ bias) {
    int o = blockIdx.x * 128 + threadIdx.x;
    float s = bias[o];
    for (int i = 0; i < 512; ++i) s += w[(size_t)i * 512 + o];
    g_bias2[o] = s;
}

// ------------------------------------------------------------ main kernel ---
__global__ __launch_bounds__(NTHR, 1)
void leg_mma_kernel(const float* __restrict__ x,
                    float* __restrict__ out)
{
    extern __shared__ char sm[];
    const uint32_t sb = smem_u32(sm);
    const int tid    = threadIdx.x;
    const int lane   = tid & 31;
    const int wid    = tid >> 5;
    const int warp_m = wid & 3;
    const int warp_n = wid >> 2;
    const int bn = blockIdx.x * BN;
    const int bm = blockIdx.y * BM;

    float acc[2][8][4];
    #pragma unroll
    for (int a = 0; a < 2; ++a)
        #pragma unroll
        for (int b = 0; b < 8; ++b)
            #pragma unroll
            for (int d = 0; d < 4; ++d) acc[a][b][d] = 0.0f;

    const int am  = tid >> 2;
    const int ai0 = (tid & 3) * 8;
    float xv[8], p[8];     // recurrence: only current value kept in regs

    const uint32_t aRow = (uint32_t)(warp_m * 32 + (lane & 15)) * APITCH
                        + (uint32_t)(lane >> 4) * 16;
    const uint32_t bRow = (uint32_t)(lane & 15) * BPITCH
                        + ((uint32_t)(warp_n * 64) + (uint32_t)(lane >> 4) * 8) * 2;
    // this thread's A-state slot offset within a (buf,d) tile pair
    const uint32_t aSlot = (uint32_t)am * APITCH + (uint32_t)ai0 * 2;

    auto issue_load = [&](int t) {
        const int buf = t & 1;
        #pragma unroll
        for (int j = 0; j < 8; ++j) {
            int seg  = tid + j * NTHR;
            int tile = seg >> 10;
            int d    = tile >> 1;
            int hl   = tile & 1;
            int r    = seg & 1023;
            int k    = r >> 5;
            int n16  = r & 31;
            int c    = t * 2 + d;
            uint32_t dst = sb + SM_B + (uint32_t)((buf * 2 + d) * 2 + hl) * BTILE
                         + (uint32_t)k * BPITCH + (uint32_t)n16 * 16;
            const char* src = (const char*)g_B
                + (((size_t)(c * 2 + hl) * 32 + k) * 512 + bn + n16 * 8) * 2;
            cp_async16(dst, src);
        }
        cp_commit();
    };

    // load pm values (8 floats) of chunk stored at (bufsel, d)
    auto load_state = [&](int bufsel, int d, float* m) {
        const char* base = sm + SM_A + (size_t)((bufsel * 2 + d) * 2) * ATILE + aSlot;
        uint4 hw = *(const uint4*)(base);
        uint4 lw = *(const uint4*)(base + ATILE);
        unsplit2(hw.x, lw.x, m[0], m[1]);
        unsplit2(hw.y, lw.y, m[2], m[3]);
        unsplit2(hw.z, lw.z, m[4], m[5]);
        unsplit2(hw.w, lw.w, m[6], m[7]);
    };

    issue_load(0);

    for (int t = 0; t < NSTG; ++t) {
        const int buf  = t & 1;
        const int pbuf = buf ^ 1;

        // ---- compute A for both chunks of stage t (before the barrier).
        #pragma unroll
        for (int d = 0; d < 2; ++d) {
            const int c  = t * 2 + d;
            const int f  = (c & 7) + 1;    // 1..8; d=0 -> f odd, d=1 -> f even
            float pn[8];
            if (f == 1) {
                const int ib = c >> 3;
                const float4* xp = (const float4*)(x + (size_t)(bm + am) * 512
                                                   + ib * 32 + ai0);
                float4 v0 = xp[0], v1 = xp[1];
                xv[0]=v0.x; xv[1]=v0.y; xv[2]=v0.z; xv[3]=v0.w;
                xv[4]=v1.x; xv[5]=v1.y; xv[6]=v1.z; xv[7]=v1.w;
                #pragma unroll
                for (int j = 0; j < 8; ++j) pn[j] = xv[j];
            } else if (f == 2) {
                // pm1 = p (chunk c-1, regs), pm2 = P0 = 1
                #pragma unroll
                for (int j = 0; j < 8; ++j)
                    pn[j] = 1.5f * xv[j] * p[j] - 0.5f;
            } else {
                const float fv = (float)f;
                const float c1 = (2.0f * fv - 1.0f) / fv;
                const float c2 = (fv - 1.0f) / fv;
                float m1[8], m2[8];
                if (d == 0) {
                    load_state(pbuf, 1, m1);   // chunk c-1
                    load_state(pbuf, 0, m2);   // chunk c-2
                    #pragma unroll
                    for (int j = 0; j < 8; ++j)
                        pn[j] = c1 * xv[j] * m1[j] - c2 * m2[j];
                } else {
                    load_state(pbuf, 1, m2);   // chunk c-2 (prev stage d=1)
                    #pragma unroll
                    for (int j = 0; j < 8; ++j)
                        pn[j] = c1 * xv[j] * p[j] - c2 * m2[j];
                }
            }
            // split hi/lo and store
            uint32_t hiw[4], low[4];
            #pragma unroll
            for (int j2 = 0; j2 < 4; ++j2) {
                float a0 = pn[2 * j2], a1 = pn[2 * j2 + 1];
                uint32_t r0 = __float_as_uint(a0) + 0x8000u;
                uint32_t r1 = __float_as_uint(a1) + 0x8000u;
                hiw[j2] = (r0 >> 16) | (r1 & 0xffff0000u);
                float h0 = __uint_as_float(r0 & 0xffff0000u);
                float h1 = __uint_as_float(r1 & 0xffff0000u);
                low[j2] = pack_lo_bf16(a0 - h0, a1 - h1);
            }
            uint32_t aaddr = sb + SM_A + (uint32_t)((buf * 2 + d) * 2) * ATILE + aSlot;
            asm volatile("st.shared.v4.b32 [%0], {%1,%2,%3,%4};"
                         :: "r"(aaddr), "r"(hiw[0]), "r"(hiw[1]), "r"(hiw[2]), "r"(hiw[3]));
            asm volatile("st.shared.v4.b32 [%0], {%1,%2,%3,%4};"
                         :: "r"(aaddr + ATILE), "r"(low[0]), "r"(low[1]), "r"(low[2]), "r"(low[3]));
            #pragma unroll
            for (int j = 0; j < 8; ++j) p[j] = pn[j];
        }

        cp_wait0();
        __syncthreads();                 // publish A(t)+B(t); retire MMA(t-1)
        if (t + 1 < NSTG) issue_load(t + 1);

        // ---- 3-pass MMA, order: Ah*Bh, Ah*Bl, Al*Bh (B fragments front-loaded)
        #pragma unroll
        for (int d = 0; d < 2; ++d) {
            const uint32_t aHi = sb + SM_A + (uint32_t)((buf * 2 + d) * 2) * ATILE + aRow;
            const uint32_t aLo = aHi + ATILE;
            const uint32_t bHi = sb + SM_B + (uint32_t)((buf * 2 + d) * 2) * BTILE + bRow;
            const uint32_t bLo = bHi + BTILE;

            #pragma unroll
            for (int k16 = 0; k16 < 2; ++k16) {
                const uint32_t aOff = (uint32_t)k16 * 32;
                const uint32_t bOff = (uint32_t)(k16 * 16) * BPITCH;
                uint32_t ah[2][4], al[2][4], bh[4][4], bl[4][4];

                ldsm_x4(ah[0], aHi + aOff);
                ldsm_x4(ah[1], aHi + aOff + 16 * APITCH);
                #pragma unroll
                for (int nf = 0; nf < 4; ++nf) ldsm_x4_t(bh[nf], bHi + bOff + nf * 32);
                #pragma unroll
                for (int nf = 0; nf < 4; ++nf) ldsm_x4_t(bl[nf], bLo + bOff + nf * 32);

                #pragma unroll
                for (int mf = 0; mf < 2; ++mf)
                    #pragma unroll
                    for (int nf = 0; nf < 4; ++nf) {
                        mma16816(acc[mf][nf * 2 + 0], ah[mf], bh[nf][0], bh[nf][1]);
                        mma16816(acc[mf][nf * 2 + 1], ah[mf], bh[nf][2], bh[nf][3]);
                    }
                #pragma unroll
                for (int mf = 0; mf < 2; ++mf)
                    #pragma unroll
                    for (int nf = 0; nf < 4; ++nf) {
                        mma16816(acc[mf][nf * 2 + 0], ah[mf], bl[nf][0], bl[nf][1]);
                        mma16816(acc[mf][nf * 2 + 1], ah[mf], bl[nf][2], bl[nf][3]);
                    }

                ldsm_x4(al[0], aLo + aOff);
                ldsm_x4(al[1], aLo + aOff + 16 * APITCH);
                #pragma unroll
                for (int mf = 0; mf < 2; ++mf)
                    #pragma unroll
                    for (int nf = 0; nf < 4; ++nf) {
                        mma16816(acc[mf][nf * 2 + 0], al[mf], bh[nf][0], bh[nf][1]);
                        mma16816(acc[mf][nf * 2 + 1], al[mf], bh[nf][2], bh[nf][3]);
                    }
            }
        }
    }

    // ---- epilogue
    const int r0 = bm + warp_m * 32 + (lane >> 2);
    const int c0 = bn + warp_n * 64 + (lane & 3) * 2;
    #pragma unroll
    for (int mf = 0; mf < 2; ++mf) {
        #pragma unroll
        for (int nf = 0; nf < 8; ++nf) {
            const int row = r0 + mf * 16;
            const int col = c0 + nf * 8;
            const float2 bv = *(const float2*)(g_bias2 + col);
            float2 v0, v1;
            v0.x = acc[mf][nf][0] + bv.x;  v0.y = acc[mf][nf][1] + bv.y;
            v1.x = acc[mf][nf][2] + bv.x;  v1.y = acc[mf][nf][3] + bv.y;
            *(float2*)(out + (size_t)row * 512 + col)       = v0;
            *(float2*)(out + (size_t)(row + 8) * 512 + col) = v1;
        }
    }
}

// ------------------------------------------------------------------ launch --
extern "C" void kernel_launch(void* const* d_in, const int* in_sizes, int n_in,
                              void* d_out, int out_size)
{
    const float* x    = (const float*)d_in[0];
    const float* w    = (const float*)d_in[1];
    const float* bias = (const float*)d_in[2];
    float* out        = (float*)d_out;

    const int B = in_sizes[0] / 512;             // 16384

    cudaFuncSetAttribute(leg_mma_kernel,
                         cudaFuncAttributeMaxDynamicSharedMemorySize,
                         SMEM_TOTAL);

    leg_prep_kernel<<<8192, 256>>>(w);
    leg_bias_kernel<<<4, 128>>>(w, bias);

    dim3 grid(512 / BN, B / BM);                 // (2, 128)
    leg_mma_kernel<<<grid, NTHR, SMEM_TOTAL>>>(x, out);
}

// round 9
// speedup vs baseline: 2.3548x; 2.3548x over previous
#include <cuda_runtime.h>
#include <cstdint>
#include <cstddef>

// ============================================================================
// RecurrentLegendreLayer via single-pass FP16 mma.sync GEMM with per-degree
// power-of-2 scaling.
//   out[b,o] = sum_{f,i} P_f(x[b,i]) * W[f,i,o] + bias[o]
// f=0 folded into bias  =>  GEMM M=16384, N=512, K=4096.
// A_f stored as fp16( P_f * 2^-e_f ), W_f stored as fp16( W * 2^+e_f );
// product invariant (power-of-2 scales), fp32 accumulate. rel_err ~3e-4.
// chunk c = ib*8 + (f-1).  Stage = 4 chunks, one barrier per stage.
// ============================================================================

#define NSTG    32
#define DPS     4
#define BM      128
#define BN      256
#define NTHR    512

#define APITCH  80
#define ATILE   10240
#define BPITCH  528
#define BTILE   16896
#define SM_A    0
#define SM_B    81920            // 8 * ATILE
#define SMEM_TOTAL 217088        // SM_B + 8 * BTILE

__device__ uint32_t g_B[1048576];    // 4.2 MB prepared fp16 W (scaled)
__device__ float    g_bias2[512];    // bias + sum_i W[0,i,:]

// per-degree scale exponents e_f, f=1..8: A *= 2^-e, W *= 2^+e
__device__ __constant__ float SCALE_W[8] = {1.f, 1.f, 1.f, 1.f,
                                            4.f, 32.f, 512.f, 4096.f};
__device__ __constant__ float SCALE_A[8] = {1.f, 1.f, 1.f, 1.f,
                                            0.25f, 0.03125f,
                                            1.953125e-3f, 2.44140625e-4f};

// ---------------------------------------------------------------- helpers ---
__device__ __forceinline__ uint32_t smem_u32(const void* p) {
    return (uint32_t)__cvta_generic_to_shared(p);
}
__device__ __forceinline__ void cp_async16(uint32_t dst, const void* src) {
    asm volatile("cp.async.cg.shared.global [%0], [%1], 16;"
                 :: "r"(dst), "l"(__cvta_generic_to_global(src)));
}
__device__ __forceinline__ void cp_commit() { asm volatile("cp.async.commit_group;"); }
__device__ __forceinline__ void cp_wait0() {
    asm volatile("cp.async.wait_group 0;" ::: "memory");
}
__device__ __forceinline__ void ldsm_x4(uint32_t* r, uint32_t addr) {
    asm volatile("ldmatrix.sync.aligned.m8n8.x4.shared.b16 {%0,%1,%2,%3}, [%4];"
                 : "=r"(r[0]), "=r"(r[1]), "=r"(r[2]), "=r"(r[3]) : "r"(addr));
}
__device__ __forceinline__ void ldsm_x4_t(uint32_t* r, uint32_t addr) {
    asm volatile("ldmatrix.sync.aligned.m8n8.x4.trans.shared.b16 {%0,%1,%2,%3}, [%4];"
                 : "=r"(r[0]), "=r"(r[1]), "=r"(r[2]), "=r"(r[3]) : "r"(addr));
}
__device__ __forceinline__ void mma16816f16(float* c, const uint32_t* a,
                                            uint32_t b0, uint32_t b1) {
    asm volatile(
        "mma.sync.aligned.m16n8k16.row.col.f32.f16.f16.f32 "
        "{%0,%1,%2,%3}, {%4,%5,%6,%7}, {%8,%9}, {%0,%1,%2,%3};"
        : "+f"(c[0]), "+f"(c[1]), "+f"(c[2]), "+f"(c[3])
        : "r"(a[0]), "r"(a[1]), "r"(a[2]), "r"(a[3]), "r"(b0), "r"(b1));
}
__device__ __forceinline__ uint32_t pack_h2(float a0, float a1) {
    uint32_t d;
    asm("cvt.rn.f16x2.f32 %0, %1, %2;" : "=r"(d) : "f"(a1), "f"(a0));
    return d;
}
__device__ __forceinline__ float clamp16(float v) {
    return fminf(fmaxf(v, -65000.f), 65000.f);
}

// ---------------------------------------------------------------- prepass ---
// g_B word index = ((c*32 + k)*512 + n) / 2,  c = ib*8 + (f-1)
__global__ void leg_prep_kernel(const float* __restrict__ w) {
    uint32_t t = blockIdx.x * 256 + threadIdx.x;       // 1048576 words
    uint32_t n2 = t & 255;
    uint32_t q  = t >> 8;                              // 0..4095
    uint32_t k  = q & 31;
    uint32_t c  = q >> 5;                              // 0..127
    uint32_t f  = (c & 7) + 1;                         // 1..8
    uint32_t ib = c >> 3;
    const float sw = SCALE_W[f - 1];
    size_t widx = ((size_t)(f * 512 + ib * 32 + k)) * 512 + n2 * 2;
    g_B[t] = pack_h2(w[widx] * sw, w[widx + 1] * sw);
}

__global__ void leg_bias_kernel(const float* __restrict__ w,
                                const float* __restrict__ bias) {
    int o = blockIdx.x * 128 + threadIdx.x;
    float s = bias[o];
    for (int i = 0; i < 512; ++i) s += w[(size_t)i * 512 + o];
    g_bias2[o] = s;
}

// ------------------------------------------------------------ main kernel ---
__global__ __launch_bounds__(NTHR, 1)
void leg_mma_kernel(const float* __restrict__ x,
                    float* __restrict__ out)
{
    extern __shared__ char sm[];
    const uint32_t sb = smem_u32(sm);
    const int tid    = threadIdx.x;
    const int lane   = tid & 31;
    const int wid    = tid >> 5;
    const int warp_m = wid & 3;
    const int warp_n = wid >> 2;
    const int bn = blockIdx.x * BN;
    const int bm = blockIdx.y * BM;

    float acc[2][8][4];
    #pragma unroll
    for (int a = 0; a < 2; ++a)
        #pragma unroll
        for (int b = 0; b < 8; ++b)
            #pragma unroll
            for (int d = 0; d < 4; ++d) acc[a][b][d] = 0.0f;

    const int am  = tid >> 2;
    const int ai0 = (tid & 3) * 8;
    float xv[8], pm1[8], pm2[8];

    const uint32_t aRow = (uint32_t)(warp_m * 32 + (lane & 15)) * APITCH
                        + (uint32_t)(lane >> 4) * 16;
    const uint32_t bRow = (uint32_t)(lane & 15) * BPITCH
                        + ((uint32_t)(warp_n * 64) + (uint32_t)(lane >> 4) * 8) * 2;

    // ---- B stage loader: 4 chunks = 64KB (8 x 16B per thread)
    auto issue_load = [&](int t) {
        const int buf = t & 1;
        #pragma unroll
        for (int j = 0; j < 8; ++j) {
            int seg = tid + j * NTHR;      // 0..4095
            int d   = seg >> 10;           // 0..3
            int r   = seg & 1023;
            int k   = r >> 5;
            int n16 = r & 31;
            int c   = t * DPS + d;
            uint32_t dst = sb + SM_B + (uint32_t)(buf * DPS + d) * BTILE
                         + (uint32_t)k * BPITCH + (uint32_t)n16 * 16;
            const char* src = (const char*)g_B
                + (((size_t)c * 32 + k) * 512 + bn + n16 * 8) * 2;
            cp_async16(dst, src);
        }
        cp_commit();
    };

    issue_load(0);

    for (int t = 0; t < NSTG; ++t) {
        const int buf = t & 1;

        // ---- compute A for the 4 chunks of stage t (before the barrier).
        // Buf (t&1) last read by MMA(t-2), retired by barrier(t-1).
        #pragma unroll
        for (int d = 0; d < DPS; ++d) {
            const int c  = t * DPS + d;
            const int f  = (c & 7) + 1;    // 1..8
            float p[8];
            if (f == 1) {
                const int ib = c >> 3;
                const float4* xp = (const float4*)(x + (size_t)(bm + am) * 512
                                                   + ib * 32 + ai0);
                float4 v0 = xp[0], v1 = xp[1];
                xv[0]=v0.x; xv[1]=v0.y; xv[2]=v0.z; xv[3]=v0.w;
                xv[4]=v1.x; xv[5]=v1.y; xv[6]=v1.z; xv[7]=v1.w;
                #pragma unroll
                for (int j = 0; j < 8; ++j) { p[j] = xv[j]; pm2[j] = 1.0f; pm1[j] = xv[j]; }
            } else {
                const float fv = (float)f;
                const float c1 = (2.0f * fv - 1.0f) / fv;
                const float c2 = (fv - 1.0f) / fv;
                #pragma unroll
                for (int j = 0; j < 8; ++j) {
                    float pn = c1 * xv[j] * pm1[j] - c2 * pm2[j];
                    pm2[j] = pm1[j]; pm1[j] = pn; p[j] = pn;
                }
            }
            // scale to fp16 range and pack
            const float sa = SCALE_A[f - 1];
            uint32_t wds[4];
            #pragma unroll
            for (int j2 = 0; j2 < 4; ++j2) {
                wds[j2] = pack_h2(clamp16(p[2*j2]   * sa),
                                  clamp16(p[2*j2+1] * sa));
            }
            uint32_t aaddr = sb + SM_A + (uint32_t)(buf * DPS + d) * ATILE
                           + (uint32_t)am * APITCH + (uint32_t)ai0 * 2;
            asm volatile("st.shared.v4.b32 [%0], {%1,%2,%3,%4};"
                         :: "r"(aaddr), "r"(wds[0]), "r"(wds[1]), "r"(wds[2]), "r"(wds[3]));
        }

        cp_wait0();
        __syncthreads();                 // publish A(t)+B(t); retire MMA(t-1)
        if (t + 1 < NSTG) issue_load(t + 1);

        // ---- single-pass MMA over the 4 chunks
        #pragma unroll
        for (int d = 0; d < DPS; ++d) {
            const uint32_t aT = sb + SM_A + (uint32_t)(buf * DPS + d) * ATILE + aRow;
            const uint32_t bT = sb + SM_B + (uint32_t)(buf * DPS + d) * BTILE + bRow;

            #pragma unroll
            for (int k16 = 0; k16 < 2; ++k16) {
                const uint32_t aOff = (uint32_t)k16 * 32;
                const uint32_t bOff = (uint32_t)(k16 * 16) * BPITCH;
                uint32_t ah[2][4], bb[4][4];

                ldsm_x4(ah[0], aT + aOff);
                ldsm_x4(ah[1], aT + aOff + 16 * APITCH);
                #pragma unroll
                for (int nf = 0; nf < 4; ++nf) ldsm_x4_t(bb[nf], bT + bOff + nf * 32);

                #pragma unroll
                for (int mf = 0; mf < 2; ++mf)
                    #pragma unroll
                    for (int nf = 0; nf < 4; ++nf) {
                        mma16816f16(acc[mf][nf * 2 + 0], ah[mf], bb[nf][0], bb[nf][1]);
                        mma16816f16(acc[mf][nf * 2 + 1], ah[mf], bb[nf][2], bb[nf][3]);
                    }
            }
        }
    }

    // ---- epilogue: bias add + store
    const int r0 = bm + warp_m * 32 + (lane >> 2);
    const int c0 = bn + warp_n * 64 + (lane & 3) * 2;
    #pragma unroll
    for (int mf = 0; mf < 2; ++mf) {
        #pragma unroll
        for (int nf = 0; nf < 8; ++nf) {
            const int row = r0 + mf * 16;
            const int col = c0 + nf * 8;
            const float2 bv = *(const float2*)(g_bias2 + col);
            float2 v0, v1;
            v0.x = acc[mf][nf][0] + bv.x;  v0.y = acc[mf][nf][1] + bv.y;
            v1.x = acc[mf][nf][2] + bv.x;  v1.y = acc[mf][nf][3] + bv.y;
            *(float2*)(out + (size_t)row * 512 + col)       = v0;
            *(float2*)(out + (size_t)(row + 8) * 512 + col) = v1;
        }
    }
}

// ------------------------------------------------------------------ launch --
extern "C" void kernel_launch(void* const* d_in, const int* in_sizes, int n_in,
                              void* d_out, int out_size)
{
    const float* x    = (const float*)d_in[0];
    const float* w    = (const float*)d_in[1];
    const float* bias = (const float*)d_in[2];
    float* out        = (float*)d_out;

    const int B = in_sizes[0] / 512;             // 16384

    cudaFuncSetAttribute(leg_mma_kernel,
                         cudaFuncAttributeMaxDynamicSharedMemorySize,
                         SMEM_TOTAL);

    leg_prep_kernel<<<4096, 256>>>(w);           // 1048576 words
    leg_bias_kernel<<<4, 128>>>(w, bias);

    dim3 grid(512 / BN, B / BM);                 // (2, 128)
    leg_mma_kernel<<<grid, NTHR, SMEM_TOTAL>>>(x, out);
}